// round 1
// baseline (speedup 1.0000x reference)
#include <cuda_runtime.h>
#include <math.h>

#define B 4
#define N 8192
#define M 8192
#define EPS 1e-8f

// Scratch: per-point squared-distance minima, as int bit patterns (valid
// ordering because all values >= 0).
__device__ int g_rowmin[B * N];
__device__ int g_colmin[B * M];

// ---------------- packed f32x2 helpers ----------------
__device__ __forceinline__ unsigned long long pk2(float a, float b) {
    unsigned long long r;
    asm("mov.b64 %0, {%1, %2};" : "=l"(r) : "f"(a), "f"(b));
    return r;
}
__device__ __forceinline__ unsigned long long add2(unsigned long long a, unsigned long long b) {
    unsigned long long r;
    asm("add.rn.f32x2 %0, %1, %2;" : "=l"(r) : "l"(a), "l"(b));
    return r;
}
__device__ __forceinline__ unsigned long long mul2(unsigned long long a, unsigned long long b) {
    unsigned long long r;
    asm("mul.rn.f32x2 %0, %1, %2;" : "=l"(r) : "l"(a), "l"(b));
    return r;
}
__device__ __forceinline__ unsigned long long fma2(unsigned long long a, unsigned long long b,
                                                   unsigned long long c) {
    unsigned long long r;
    asm("fma.rn.f32x2 %0, %1, %2, %3;" : "=l"(r) : "l"(a), "l"(b), "l"(c));
    return r;
}
__device__ __forceinline__ void unpk2(unsigned long long v, float& lo, float& hi) {
    asm("mov.b64 {%0, %1}, %2;" : "=f"(lo), "=f"(hi) : "l"(v));
}

// ---------------- init ----------------
__global__ void init_kernel(float* out) {
    int tid = blockIdx.x * blockDim.x + threadIdx.x;
    const int INF_BITS = 0x7F800000;  // +inf
    if (tid < B * N) g_rowmin[tid] = INF_BITS;
    if (tid < B * M) g_colmin[tid] = INF_BITS;
    if (tid == 0) out[0] = 0.0f;
}

// ---------------- fused tile kernel ----------------
// Tile: 128 sources x 128 targets. 256 threads: 16x16, each thread an 8x8
// register sub-tile. Targets processed as f32x2 pairs.
__global__ __launch_bounds__(256) void tile_kernel(const float* __restrict__ source,
                                                   const float* __restrict__ target) {
    __shared__ __align__(16) float s_x[128], s_y[128], s_z[128];
    __shared__ __align__(16) float t_x[128], t_y[128], t_z[128];  // NEGATED targets
    __shared__ float red[128 * 17];                               // padded, conflict-free

    const int tid = threadIdx.x;
    const int b   = blockIdx.z;
    const int row0 = blockIdx.y * 128;  // source tile base
    const int col0 = blockIdx.x * 128;  // target tile base

    // Stage source tile (coordinate-split)
    const float* sp = source + ((long)b * N + row0) * 3;
    for (int idx = tid; idx < 384; idx += 256) {
        float v = sp[idx];
        int p = idx / 3, c = idx - 3 * p;
        if (c == 0) s_x[p] = v; else if (c == 1) s_y[p] = v; else s_z[p] = v;
    }
    // Stage target tile, negated (so sub == add in packed math)
    const float* tp = target + ((long)b * M + col0) * 3;
    for (int idx = tid; idx < 384; idx += 256) {
        float v = -tp[idx];
        int p = idx / 3, c = idx - 3 * p;
        if (c == 0) t_x[p] = v; else if (c == 1) t_y[p] = v; else t_z[p] = v;
    }
    __syncthreads();

    const int txi = tid & 15;
    const int tyi = tid >> 4;
    const int r0 = tyi * 8;  // local source rows r0..r0+7
    const int c0 = txi * 8;  // local target cols c0..c0+7

    // Load 4 target pairs per coordinate (LDS.64, broadcast across tyi)
    unsigned long long ntx[4], nty[4], ntz[4];
#pragma unroll
    for (int j = 0; j < 4; j++) {
        float2 vx = *reinterpret_cast<const float2*>(&t_x[c0 + 2 * j]);
        float2 vy = *reinterpret_cast<const float2*>(&t_y[c0 + 2 * j]);
        float2 vz = *reinterpret_cast<const float2*>(&t_z[c0 + 2 * j]);
        ntx[j] = pk2(vx.x, vx.y);
        nty[j] = pk2(vy.x, vy.y);
        ntz[j] = pk2(vz.x, vz.y);
    }

    float rmin[8], cmin[8];
#pragma unroll
    for (int i = 0; i < 8; i++) { rmin[i] = 3.4e38f; cmin[i] = 3.4e38f; }

#pragma unroll
    for (int i = 0; i < 8; i++) {
        float sx = s_x[r0 + i], sy = s_y[r0 + i], sz = s_z[r0 + i];
        unsigned long long sxd = pk2(sx, sx);
        unsigned long long syd = pk2(sy, sy);
        unsigned long long szd = pk2(sz, sz);
#pragma unroll
        for (int j = 0; j < 4; j++) {
            unsigned long long dx = add2(sxd, ntx[j]);   // s - t (targets negated)
            unsigned long long dy = add2(syd, nty[j]);
            unsigned long long dz = add2(szd, ntz[j]);
            unsigned long long d  = mul2(dx, dx);
            d = fma2(dy, dy, d);
            d = fma2(dz, dz, d);
            float dlo, dhi;
            unpk2(d, dlo, dhi);
            rmin[i]          = fminf(rmin[i], dlo);
            rmin[i]          = fminf(rmin[i], dhi);
            cmin[2 * j]      = fminf(cmin[2 * j], dlo);
            cmin[2 * j + 1]  = fminf(cmin[2 * j + 1], dhi);
        }
    }

    // ---- CTA reduction: row mins (across txi) ----
#pragma unroll
    for (int i = 0; i < 8; i++) red[(r0 + i) * 17 + txi] = rmin[i];
    __syncthreads();
    if (tid < 128) {
        float m = red[tid * 17];
#pragma unroll
        for (int k = 1; k < 16; k++) m = fminf(m, red[tid * 17 + k]);
        atomicMin(&g_rowmin[b * N + row0 + tid], __float_as_int(m));
    }
    __syncthreads();

    // ---- CTA reduction: col mins (across tyi) ----
#pragma unroll
    for (int k = 0; k < 8; k++) red[(c0 + k) * 17 + tyi] = cmin[k];
    __syncthreads();
    if (tid < 128) {
        float m = red[tid * 17];
#pragma unroll
        for (int k = 1; k < 16; k++) m = fminf(m, red[tid * 17 + k]);
        atomicMin(&g_colmin[b * M + col0 + tid], __float_as_int(m));
    }
}

// ---------------- finalize ----------------
// forward = mean over B*N of sqrt(rowmin+EPS)*w ; backward = mean over B*M of sqrt(colmin+EPS)
__global__ void finalize_kernel(const float* __restrict__ weights, float* __restrict__ out) {
    __shared__ float sred[256];
    int tid = blockIdx.x * blockDim.x + threadIdx.x;
    float v = 0.0f;
    if (tid < B * N) {
        float d2 = __int_as_float(g_rowmin[tid]);
        v = sqrtf(d2 + EPS) * weights[tid] * (1.0f / (B * N));
    } else {
        int t = tid - B * N;
        float d2 = __int_as_float(g_colmin[t]);
        v = sqrtf(d2 + EPS) * (1.0f / (B * M));
    }
    sred[threadIdx.x] = v;
    __syncthreads();
    for (int s = 128; s > 0; s >>= 1) {
        if (threadIdx.x < s) sred[threadIdx.x] += sred[threadIdx.x + s];
        __syncthreads();
    }
    if (threadIdx.x == 0) atomicAdd(out, sred[0]);
}

extern "C" void kernel_launch(void* const* d_in, const int* in_sizes, int n_in,
                              void* d_out, int out_size) {
    const float* source  = (const float*)d_in[0];
    const float* target  = (const float*)d_in[1];
    const float* weights = (const float*)d_in[2];
    float* out = (float*)d_out;

    init_kernel<<<(B * N + 255) / 256, 256>>>(out);

    dim3 grid(M / 128, N / 128, B);
    tile_kernel<<<grid, 256>>>(source, target);

    finalize_kernel<<<(B * N + B * M) / 256, 256>>>(weights, out);
}